// round 11
// baseline (speedup 1.0000x reference)
#include <cuda_runtime.h>
#include <math.h>

#define NSAMP   480000
#define SRATE   48000.0f
#define MAXDEL  50
#define BLK     384
#define NBLK    125                 // <= 148 SMs -> all CTAs co-resident (grid-sync safe)
#define M_PER   10                  // NSAMP / (NBLK*BLK)
#define SEG     (BLK * M_PER)       // 3840 samples per block
#define NTHREADS (NBLK * BLK)       // 48000

// comb fast-path constants (hold for this dataset: p0 in [0,1) -> freq clips to 20)
#define CHN     2400                // L
#define CLEN    200                 // NSAMP / L
#define NDEL    50                  // min(CLEN, MAXDEL)
#define PQ      20                  // subchains per chain (NTHREADS / CHN)
#define SUBLEN  10                  // CLEN / PQ

// scratch (static device globals — no allocation)
__device__ float g_bpart_lo[NBLK];
__device__ float g_bpart_hi[NBLK];
__device__ float g_filt[NSAMP];
__device__ unsigned int g_bar0 = 0;
__device__ unsigned int g_bar1 = 0;
__device__ unsigned int g_bar2 = 0;

struct RParams {
    float a_lo, a_hi, fb, gain;
    int L, nd;
};

__device__ __forceinline__ RParams get_params(const float* __restrict__ p) {
    RParams r;
    float freq = fminf(fmaxf(p[0], 20.0f), SRATE * 0.5f);
    r.fb   = fminf(fmaxf(p[1], 0.0f), 0.99f);
    r.a_lo = fminf(fmaxf(p[2], 1e-7f), 0.99f);
    r.a_hi = fminf(fmaxf(p[3], 1e-7f), 0.99f);
    r.gain = fmaxf(p[4], 1e-7f);
    float dl = floorf(SRATE / freq);
    dl = fminf(fmaxf(dl, 1.0f), (float)(NSAMP / 2));
    r.L = (int)dl;
    int nd = NSAMP / r.L;
    r.nd = nd < MAXDEL ? nd : MAXDEL;
    return r;
}

// grid-wide barrier: all 125 CTAs are resident, so spinning is deadlock-free.
__device__ __forceinline__ void grid_barrier(unsigned int* ctr) {
    __threadfence();
    __syncthreads();
    if (threadIdx.x == 0) {
        atomicAdd(ctr, 1u);
        while (*(volatile unsigned int*)ctr < (unsigned)NBLK) { }
    }
    __syncthreads();
    __threadfence();
}

__global__ __launch_bounds__(BLK) void resonator_fused(
    const float* __restrict__ in_sig, const float* __restrict__ p,
    const float* __restrict__ buf, float* __restrict__ out)
{
    __shared__ float s[SEG];
    __shared__ float sv_lo[BLK], sv_hi[BLK];

    const int t = threadIdx.x;
    const int b = blockIdx.x;
    const int base = b * SEG;
    const int gtid = b * BLK + t;

    // ---- stage raw segment (float4, coalesced) ----
    {
        const float4* in4 = (const float4*)(buf + base);
        float4* s4 = (float4*)s;
        for (int i = t; i < SEG / 4; i += BLK) s4[i] = in4[i];
    }

    // ---- prefetch this thread's phase-3 in_sig lines into L2 ----
    // (addresses match the fast-path mapping; always in-bounds, harmless otherwise)
    {
        const int q = gtid / CHN;
        const int c = gtid - q * CHN;
        const float* ip = in_sig + c + (q * SUBLEN) * CHN;
#pragma unroll
        for (int jj = 0; jj < SUBLEN; jj++)
            asm volatile("prefetch.global.L2 [%0];" :: "l"(ip + jj * CHN));
    }
    __syncthreads();

    const RParams rp = get_params(p);
    const float a_lo = rp.a_lo, d_lo = 1.0f - rp.a_lo;
    const float a_hi = rp.a_hi, d_hi = 1.0f - rp.a_hi;

    // ---- phase 1: per-thread partials (zero init), in-block affine scan ----
    {
        float ylo = 0.0f, yhi = 0.0f;
        const int off = t * M_PER;
#pragma unroll
        for (int k = 0; k < M_PER; k++) {
            float x = s[off + k];
            ylo = fmaf(a_lo, x, d_lo * ylo);
            yhi = fmaf(a_hi, x, d_hi * yhi);
        }
        sv_lo[t] = ylo;
        sv_hi[t] = yhi;
    }

    // D = d^M_PER
    float Plo = 1.0f, Phi = 1.0f;
#pragma unroll
    for (int k = 0; k < M_PER; k++) { Plo *= d_lo; Phi *= d_hi; }
    __syncthreads();

    // inclusive affine scan over 384 threads: 9 rounds (gap up to 256)
    float lad_lo[9], lad_hi[9];
#pragma unroll
    for (int r = 0; r < 9; r++) {
        lad_lo[r] = Plo; lad_hi[r] = Phi;           // D^(2^r)
        const int gap = 1 << r;
        float mylo = sv_lo[t], myhi = sv_hi[t];
        float olo = 0.0f, ohi = 0.0f;
        if (t >= gap) { olo = sv_lo[t - gap]; ohi = sv_hi[t - gap]; }
        __syncthreads();
        sv_lo[t] = fmaf(Plo, olo, mylo);
        sv_hi[t] = fmaf(Phi, ohi, myhi);
        __syncthreads();
        Plo *= Plo; Phi *= Phi;
    }

    // exclusive prefix + D^t (into registers BEFORE sv gets reused)
    const float vex_lo = (t == 0) ? 0.0f : sv_lo[t - 1];
    const float vex_hi = (t == 0) ? 0.0f : sv_hi[t - 1];
    float pex_lo = 1.0f, pex_hi = 1.0f;
#pragma unroll
    for (int r = 0; r < 9; r++)
        if ((t >> r) & 1) { pex_lo *= lad_lo[r]; pex_hi *= lad_hi[r]; }

    if (t == BLK - 1) {
        g_bpart_lo[b] = sv_lo[t];
        g_bpart_hi[b] = sv_hi[t];
    }

    grid_barrier(&g_bar0);

    // ---- phase 2: parallel scan of 125 block partials (every block, redundant)
    // multiplier = block decay B = D^384 = D^256 * D^128
    const float Bl = lad_lo[8] * lad_lo[7];
    const float Bh = lad_hi[8] * lad_hi[7];
    {
        float vlo = 0.0f, vhi = 0.0f;
        if (t < NBLK) { vlo = g_bpart_lo[t]; vhi = g_bpart_hi[t]; }
        sv_lo[t] = vlo;
        sv_hi[t] = vhi;
        __syncthreads();
#pragma unroll
        for (int r = 0; r < 7; r++) {               // gap up to 64 covers 125
            const int gap = 1 << r;
            float mylo = sv_lo[t], myhi = sv_hi[t];
            float olo = 0.0f, ohi = 0.0f;
            if (t >= gap && t < NBLK) { olo = sv_lo[t - gap]; ohi = sv_hi[t - gap]; }
            __syncthreads();
            sv_lo[t] = fmaf(Bl, olo, mylo);
            sv_hi[t] = fmaf(Bh, ohi, myhi);
            __syncthreads();
        }
    }
    // this block's exclusive carry
    const float Cb_lo = (b == 0) ? 0.0f : sv_lo[b - 1];
    const float Cb_hi = (b == 0) ? 0.0f : sv_hi[b - 1];
    __syncthreads();   // everyone done reading sv

    // ---- replay with exact carry, write filtered = y_hi - y_lo ----
    {
        float ylo = fmaf(pex_lo, Cb_lo, vex_lo);
        float yhi = fmaf(pex_hi, Cb_hi, vex_hi);
        const int off = t * M_PER;
#pragma unroll
        for (int k = 0; k < M_PER; k++) {
            float x = s[off + k];
            ylo = fmaf(a_lo, x, d_lo * ylo);
            yhi = fmaf(a_hi, x, d_hi * yhi);
            s[off + k] = yhi - ylo;
        }
    }
    __syncthreads();
    {
        float4* f4 = (float4*)(g_filt + base);
        const float4* s4 = (const float4*)s;
        for (int i = t; i < SEG / 4; i += BLK) f4[i] = s4[i];
    }

    grid_barrier(&g_bar1);

    // ---- phase 3: comb + tanh ----
    const float fb = rp.fb, gain = rp.gain;

    if (rp.L == CHN && rp.nd == NDEL) {
        // fast path: per-chain stride-L recurrence
        // T[j] = fb*(f[j-1] + T[j-1]) - fb^50 * f[j-50]   (tail when j>=50)
        const int q = gtid / CHN;                   // subchain index (0..19)
        const int c = gtid - q * CHN;               // chain id (coalesced in warp)
        const int j0 = q * SUBLEN;

        // fb^50 by squaring
        const float fp2 = fb * fb;
        const float fp4 = fp2 * fp2;
        const float fp8 = fp4 * fp4;
        const float fp16 = fp8 * fp8;
        const float fb25 = fp16 * fp8 * fb;
        const float fb50 = fb25 * fb25;

        const float* __restrict__ fc = g_filt + c;

        // startup: T[j0] = sum_{i=1..min(49,j0)} fb^i f[j0-i], MLP=8
        float T;
        {
            const int im = min(NDEL - 1, j0);
            const float fb3 = fp2 * fb;
            const float fb5 = fp4 * fb, fb6 = fp4 * fp2, fb7 = fp4 * fb3;
            float s0 = 0.f, s1 = 0.f, s2 = 0.f, s3 = 0.f;
            float s4 = 0.f, s5 = 0.f, s6 = 0.f, s7 = 0.f;
            float w = fb;
            int i = 1;
            for (; i + 7 <= im; i += 8) {
                const float* qp = fc + (j0 - i) * CHN;
                s0 = fmaf(w,        __ldg(qp),           s0);
                s1 = fmaf(w * fb,   __ldg(qp - CHN),     s1);
                s2 = fmaf(w * fp2,  __ldg(qp - 2 * CHN), s2);
                s3 = fmaf(w * fb3,  __ldg(qp - 3 * CHN), s3);
                s4 = fmaf(w * fp4,  __ldg(qp - 4 * CHN), s4);
                s5 = fmaf(w * fb5,  __ldg(qp - 5 * CHN), s5);
                s6 = fmaf(w * fb6,  __ldg(qp - 6 * CHN), s6);
                s7 = fmaf(w * fb7,  __ldg(qp - 7 * CHN), s7);
                w *= fp8;
            }
            for (; i <= im; i++) {
                s0 = fmaf(w, __ldg(fc + (j0 - i) * CHN), s0);
                w *= fb;
            }
            T = ((s0 + s1) + (s2 + s3)) + ((s4 + s5) + (s6 + s7));
        }
        {
            const int n = c + j0 * CHN;
            out[n] = tanhf((__ldg(in_sig + n) + T) * gain);
        }

        // recurrence over the subchain
        float fj = __ldg(fc + j0 * CHN);            // f[j-1] for j = j0+1
#pragma unroll
        for (int jj = 1; jj < SUBLEN; jj++) {
            const int j = j0 + jj;
            float tail = (j >= NDEL) ? __ldg(fc + (j - NDEL) * CHN) : 0.0f;
            T = fmaf(fb, fj + T, -fb50 * tail);
            const int n = c + j * CHN;
            float fnext = __ldg(fc + j * CHN);
            out[n] = tanhf((__ldg(in_sig + n) + T) * gain);
            fj = fnext;
        }
    } else {
        // generic fallback: direct gather, grid-stride
        const int L = rp.L;
        const float fb2 = fb * fb, fb3 = fb2 * fb, fb4 = fb2 * fb2;
        for (int n = gtid; n < NSAMP; n += NTHREADS) {
            const int imax = min(rp.nd - 1, n / L);
            const float* __restrict__ basep = g_filt + n;
            float s0 = 0.0f, s1 = 0.0f, s2 = 0.0f, s3 = 0.0f;
            float w = fb;
            int i = 1;
            for (; i + 3 <= imax; i += 4) {
                const float* qp = basep - i * L;
                s0 = fmaf(w,       __ldg(qp),         s0);
                s1 = fmaf(w * fb,  __ldg(qp - L),     s1);
                s2 = fmaf(w * fb2, __ldg(qp - 2 * L), s2);
                s3 = fmaf(w * fb3, __ldg(qp - 3 * L), s3);
                w *= fb4;
            }
            for (; i <= imax; i++) {
                s0 = fmaf(w, __ldg(basep - i * L), s0);
                w *= fb;
            }
            float sum = __ldg(in_sig + n) + ((s0 + s1) + (s2 + s3));
            out[n] = tanhf(sum * gain);
        }
    }

    // ---- reset barriers for the next graph replay ----
    __syncthreads();
    if (t == 0) {
        unsigned int tk = atomicAdd(&g_bar2, 1u);
        if (tk == (unsigned)(NBLK - 1)) {
            g_bar0 = 0; g_bar1 = 0; g_bar2 = 0;
        }
    }
}

// ---------------------------------------------------------------------------
extern "C" void kernel_launch(void* const* d_in, const int* in_sizes, int n_in,
                              void* d_out, int out_size)
{
    const float* input_signal = (const float*)d_in[0];
    const float* parameters   = (const float*)d_in[1];
    const float* delay_buffer = (const float*)d_in[2];
    float* out = (float*)d_out;

    resonator_fused<<<NBLK, BLK>>>(input_signal, parameters, delay_buffer, out);
}

// round 12
// speedup vs baseline: 1.2354x; 1.2354x over previous
#include <cuda_runtime.h>
#include <math.h>

#define NSAMP   480000
#define SRATE   48000.0f
#define MAXDEL  50
#define BLK     256
#define NBLK    125                 // <= 148 SMs -> all CTAs co-resident (grid-sync safe)
#define M_PER   15                  // NSAMP / (NBLK*BLK)
#define SEG     (BLK * M_PER)       // 3840 samples per block
#define NTHREADS (NBLK * BLK)       // 32000

// comb fast-path constants (hold for this dataset: p0 in [0,1) -> freq clips to 20)
#define CHN     2400                // L
#define CLEN    200                 // NSAMP / L
#define NDEL    50                  // min(CLEN, MAXDEL)
#define PQ      13                  // subchains per chain (13*2400 = 31200 <= 32000)
#define SUBLEN  16                  // ceil(CLEN / PQ)

// scratch (static device globals — no allocation)
__device__ float g_bpart_lo[NBLK];
__device__ float g_bpart_hi[NBLK];
__device__ float g_filt[NSAMP];
__device__ unsigned int g_bar0 = 0;
__device__ unsigned int g_bar1 = 0;
__device__ unsigned int g_bar2 = 0;

struct RParams {
    float a_lo, a_hi, fb, gain;
    int L, nd;
};

__device__ __forceinline__ RParams get_params(const float* __restrict__ p) {
    RParams r;
    float freq = fminf(fmaxf(p[0], 20.0f), SRATE * 0.5f);
    r.fb   = fminf(fmaxf(p[1], 0.0f), 0.99f);
    r.a_lo = fminf(fmaxf(p[2], 1e-7f), 0.99f);
    r.a_hi = fminf(fmaxf(p[3], 1e-7f), 0.99f);
    r.gain = fmaxf(p[4], 1e-7f);
    float dl = floorf(SRATE / freq);
    dl = fminf(fmaxf(dl, 1.0f), (float)(NSAMP / 2));
    r.L = (int)dl;
    int nd = NSAMP / r.L;
    r.nd = nd < MAXDEL ? nd : MAXDEL;
    return r;
}

// grid-wide barrier: all 125 CTAs are resident, so spinning is deadlock-free.
__device__ __forceinline__ void grid_barrier(unsigned int* ctr) {
    __threadfence();
    __syncthreads();
    if (threadIdx.x == 0) {
        atomicAdd(ctr, 1u);
        while (*(volatile unsigned int*)ctr < (unsigned)NBLK) { }
    }
    __syncthreads();
    __threadfence();
}

__global__ __launch_bounds__(BLK) void resonator_fused(
    const float* __restrict__ in_sig, const float* __restrict__ p,
    const float* __restrict__ buf, float* __restrict__ out)
{
    __shared__ float s[SEG];
    __shared__ float sv_lo[BLK], sv_hi[BLK];

    const int t = threadIdx.x;
    const int b = blockIdx.x;
    const int base = b * SEG;
    const int gtid = b * BLK + t;

    // ---- stage raw segment (float4, coalesced) ----
    {
        const float4* in4 = (const float4*)(buf + base);
        float4* s4 = (float4*)s;
        for (int i = t; i < SEG / 4; i += BLK) s4[i] = in4[i];
    }
    __syncthreads();

    const RParams rp = get_params(p);
    const float a_lo = rp.a_lo, d_lo = 1.0f - rp.a_lo;
    const float a_hi = rp.a_hi, d_hi = 1.0f - rp.a_hi;

    // ---- phase 1: per-thread partials (zero init), in-block affine scan ----
    {
        float ylo = 0.0f, yhi = 0.0f;
        const int off = t * M_PER;
#pragma unroll
        for (int k = 0; k < M_PER; k++) {
            float x = s[off + k];
            ylo = fmaf(a_lo, x, d_lo * ylo);
            yhi = fmaf(a_hi, x, d_hi * yhi);
        }
        sv_lo[t] = ylo;
        sv_hi[t] = yhi;
    }

    // D = d^M_PER
    float Plo = 1.0f, Phi = 1.0f;
#pragma unroll
    for (int k = 0; k < M_PER; k++) { Plo *= d_lo; Phi *= d_hi; }
    __syncthreads();

    // inclusive affine scan over 256 threads: 8 rounds
    float lad_lo[8], lad_hi[8];
#pragma unroll
    for (int r = 0; r < 8; r++) {
        lad_lo[r] = Plo; lad_hi[r] = Phi;           // D^(2^r)
        const int gap = 1 << r;
        float mylo = sv_lo[t], myhi = sv_hi[t];
        float olo = 0.0f, ohi = 0.0f;
        if (t >= gap) { olo = sv_lo[t - gap]; ohi = sv_hi[t - gap]; }
        __syncthreads();
        sv_lo[t] = fmaf(Plo, olo, mylo);
        sv_hi[t] = fmaf(Phi, ohi, myhi);
        __syncthreads();
        Plo *= Plo; Phi *= Phi;                     // ends at B = D^256 (block decay)
    }

    // exclusive prefix + D^t (into registers BEFORE sv gets reused)
    const float vex_lo = (t == 0) ? 0.0f : sv_lo[t - 1];
    const float vex_hi = (t == 0) ? 0.0f : sv_hi[t - 1];
    float pex_lo = 1.0f, pex_hi = 1.0f;
#pragma unroll
    for (int r = 0; r < 8; r++)
        if ((t >> r) & 1) { pex_lo *= lad_lo[r]; pex_hi *= lad_hi[r]; }

    if (t == BLK - 1) {
        g_bpart_lo[b] = sv_lo[t];
        g_bpart_hi[b] = sv_hi[t];
    }

    grid_barrier(&g_bar0);

    // ---- phase 2: parallel scan of 125 block partials (every block, redundant)
    // multiplier = block decay B = D^256 (Plo/Phi after the 8 rounds)
    {
        float vlo = 0.0f, vhi = 0.0f;
        if (t < NBLK) { vlo = g_bpart_lo[t]; vhi = g_bpart_hi[t]; }
        sv_lo[t] = vlo;
        sv_hi[t] = vhi;
        __syncthreads();
#pragma unroll
        for (int r = 0; r < 7; r++) {               // gap up to 64 covers 125
            const int gap = 1 << r;
            float mylo = sv_lo[t], myhi = sv_hi[t];
            float olo = 0.0f, ohi = 0.0f;
            if (t >= gap && t < NBLK) { olo = sv_lo[t - gap]; ohi = sv_hi[t - gap]; }
            __syncthreads();
            sv_lo[t] = fmaf(Plo, olo, mylo);
            sv_hi[t] = fmaf(Phi, ohi, myhi);
            __syncthreads();
        }
    }
    // this block's exclusive carry
    const float Cb_lo = (b == 0) ? 0.0f : sv_lo[b - 1];
    const float Cb_hi = (b == 0) ? 0.0f : sv_hi[b - 1];
    __syncthreads();

    // ---- replay with exact carry, write filtered = y_hi - y_lo ----
    {
        float ylo = fmaf(pex_lo, Cb_lo, vex_lo);
        float yhi = fmaf(pex_hi, Cb_hi, vex_hi);
        const int off = t * M_PER;
#pragma unroll
        for (int k = 0; k < M_PER; k++) {
            float x = s[off + k];
            ylo = fmaf(a_lo, x, d_lo * ylo);
            yhi = fmaf(a_hi, x, d_hi * yhi);
            s[off + k] = yhi - ylo;
        }
    }
    __syncthreads();
    {
        float4* f4 = (float4*)(g_filt + base);
        const float4* s4 = (const float4*)s;
        for (int i = t; i < SEG / 4; i += BLK) f4[i] = s4[i];
    }

    grid_barrier(&g_bar1);

    // ---- phase 3: comb + tanh ----
    const float fb = rp.fb, gain = rp.gain;

    if (rp.L == CHN && rp.nd == NDEL) {
        // fast path: per-chain stride-L recurrence
        // T[j] = fb*(f[j-1] + T[j-1]) - fb^50 * f[j-50]   (tail when j>=50)
        if (gtid < CHN * PQ) {
            const int q = gtid / CHN;               // subchain index (0..12)
            const int c = gtid - q * CHN;           // chain id (coalesced in warp)
            const int j0 = q * SUBLEN;
            const int j1 = min(j0 + SUBLEN, CLEN);

            // fb^50 by squaring
            const float fp2 = fb * fb;
            const float fp4 = fp2 * fp2;
            const float fp8 = fp4 * fp4;
            const float fp16 = fp8 * fp8;
            const float fb25 = fp16 * fp8 * fb;
            const float fb50 = fb25 * fb25;

            const float* __restrict__ fc = g_filt + c;
            const float* __restrict__ ic = in_sig + c;

            // ---- register preload: all loads independent, MLP ~ 3*SUBLEN ----
            float fv[SUBLEN];   // f[j0+jj]
            float tl[SUBLEN];   // f[j0+jj-50] (0 if j<50), used for jj>=1
            float iv[SUBLEN];   // in_sig at n = c + (j0+jj)*CHN
#pragma unroll
            for (int jj = 0; jj < SUBLEN; jj++) {
                const int j = j0 + jj;
                const bool v = (j < j1);
                fv[jj] = v ? __ldg(fc + j * CHN) : 0.0f;
                tl[jj] = (v && j >= NDEL) ? __ldg(fc + (j - NDEL) * CHN) : 0.0f;
                iv[jj] = v ? __ldg(ic + j * CHN) : 0.0f;
            }

            // startup: T[j0] = sum_{i=1..min(49,j0)} fb^i f[j0-i], MLP=8
            float T;
            {
                const int im = min(NDEL - 1, j0);
                const float fb3 = fp2 * fb;
                const float fb5 = fp4 * fb, fb6 = fp4 * fp2, fb7 = fp4 * fb3;
                float s0 = 0.f, s1 = 0.f, s2 = 0.f, s3 = 0.f;
                float s4 = 0.f, s5 = 0.f, s6 = 0.f, s7 = 0.f;
                float w = fb;
                int i = 1;
                for (; i + 7 <= im; i += 8) {
                    const float* qp = fc + (j0 - i) * CHN;
                    s0 = fmaf(w,        __ldg(qp),           s0);
                    s1 = fmaf(w * fb,   __ldg(qp - CHN),     s1);
                    s2 = fmaf(w * fp2,  __ldg(qp - 2 * CHN), s2);
                    s3 = fmaf(w * fb3,  __ldg(qp - 3 * CHN), s3);
                    s4 = fmaf(w * fp4,  __ldg(qp - 4 * CHN), s4);
                    s5 = fmaf(w * fb5,  __ldg(qp - 5 * CHN), s5);
                    s6 = fmaf(w * fb6,  __ldg(qp - 6 * CHN), s6);
                    s7 = fmaf(w * fb7,  __ldg(qp - 7 * CHN), s7);
                    w *= fp8;
                }
                for (; i <= im; i++) {
                    s0 = fmaf(w, __ldg(fc + (j0 - i) * CHN), s0);
                    w *= fb;
                }
                T = ((s0 + s1) + (s2 + s3)) + ((s4 + s5) + (s6 + s7));
            }

            // all-register recurrence + outputs
            out[c + j0 * CHN] = tanhf((iv[0] + T) * gain);
#pragma unroll
            for (int jj = 1; jj < SUBLEN; jj++) {
                const int j = j0 + jj;
                if (j < j1) {
                    T = fmaf(fb, fv[jj - 1] + T, -fb50 * tl[jj]);
                    out[c + j * CHN] = tanhf((iv[jj] + T) * gain);
                }
            }
        }
    } else {
        // generic fallback: direct gather, grid-stride
        const int L = rp.L;
        const float fb2 = fb * fb, fb3 = fb2 * fb, fb4 = fb2 * fb2;
        for (int n = gtid; n < NSAMP; n += NTHREADS) {
            const int imax = min(rp.nd - 1, n / L);
            const float* __restrict__ basep = g_filt + n;
            float s0 = 0.0f, s1 = 0.0f, s2 = 0.0f, s3 = 0.0f;
            float w = fb;
            int i = 1;
            for (; i + 3 <= imax; i += 4) {
                const float* qp = basep - i * L;
                s0 = fmaf(w,       __ldg(qp),         s0);
                s1 = fmaf(w * fb,  __ldg(qp - L),     s1);
                s2 = fmaf(w * fb2, __ldg(qp - 2 * L), s2);
                s3 = fmaf(w * fb3, __ldg(qp - 3 * L), s3);
                w *= fb4;
            }
            for (; i <= imax; i++) {
                s0 = fmaf(w, __ldg(basep - i * L), s0);
                w *= fb;
            }
            float sum = __ldg(in_sig + n) + ((s0 + s1) + (s2 + s3));
            out[n] = tanhf(sum * gain);
        }
    }

    // ---- reset barriers for the next graph replay ----
    __syncthreads();
    if (t == 0) {
        unsigned int tk = atomicAdd(&g_bar2, 1u);
        if (tk == (unsigned)(NBLK - 1)) {
            g_bar0 = 0; g_bar1 = 0; g_bar2 = 0;
        }
    }
}

// ---------------------------------------------------------------------------
extern "C" void kernel_launch(void* const* d_in, const int* in_sizes, int n_in,
                              void* d_out, int out_size)
{
    const float* input_signal = (const float*)d_in[0];
    const float* parameters   = (const float*)d_in[1];
    const float* delay_buffer = (const float*)d_in[2];
    float* out = (float*)d_out;

    resonator_fused<<<NBLK, BLK>>>(input_signal, parameters, delay_buffer, out);
}

// round 16
// speedup vs baseline: 1.4168x; 1.1469x over previous
#include <cuda_runtime.h>
#include <math.h>

#define NSAMP   480000
#define SRATE   48000.0f
#define MAXDEL  50
#define BLK     480                 // 15 warps/SM -> occupancy cap ~23%
#define NBLK    125                 // <= 148 SMs -> all CTAs co-resident (grid-sync safe)
#define M_PER   8                   // NSAMP / (NBLK*BLK)
#define SEG     (BLK * M_PER)       // 3840 samples per block
#define NTHREADS (NBLK * BLK)       // 60000

// comb fast-path constants (hold for this dataset: p0 in [0,1) -> freq clips to 20)
#define CHN     2400                // L
#define CLEN    200                 // NSAMP / L
#define NDEL    50                  // min(CLEN, MAXDEL)
#define PQ      25                  // subchains per chain (25*2400 = 60000 = NTHREADS)
#define SUBLEN  8                   // CLEN / PQ exactly

// scratch (static device globals — no allocation)
__device__ float g_bpart_lo[NBLK];
__device__ float g_bpart_hi[NBLK];
__device__ float g_filt[NSAMP];
__device__ unsigned int g_bar0 = 0;
__device__ unsigned int g_bar1 = 0;
__device__ unsigned int g_bar2 = 0;

struct RParams {
    float a_lo, a_hi, fb, gain;
    int L, nd;
};

__device__ __forceinline__ RParams get_params(const float* __restrict__ p) {
    RParams r;
    float freq = fminf(fmaxf(p[0], 20.0f), SRATE * 0.5f);
    r.fb   = fminf(fmaxf(p[1], 0.0f), 0.99f);
    r.a_lo = fminf(fmaxf(p[2], 1e-7f), 0.99f);
    r.a_hi = fminf(fmaxf(p[3], 1e-7f), 0.99f);
    r.gain = fmaxf(p[4], 1e-7f);
    float dl = floorf(SRATE / freq);
    dl = fminf(fmaxf(dl, 1.0f), (float)(NSAMP / 2));
    r.L = (int)dl;
    int nd = NSAMP / r.L;
    r.nd = nd < MAXDEL ? nd : MAXDEL;
    return r;
}

__device__ __forceinline__ float fast_tanh(float x) {
    float y;
    asm("tanh.approx.f32 %0, %1;" : "=f"(y) : "f"(x));
    return y;
}

// grid-wide barrier: all 125 CTAs are resident, so spinning is deadlock-free.
__device__ __forceinline__ void grid_barrier(unsigned int* ctr) {
    __threadfence();
    __syncthreads();
    if (threadIdx.x == 0) {
        atomicAdd(ctr, 1u);
        while (*(volatile unsigned int*)ctr < (unsigned)NBLK) { }
    }
    __syncthreads();
    __threadfence();
}

__global__ __launch_bounds__(BLK) void resonator_fused(
    const float* __restrict__ in_sig, const float* __restrict__ p,
    const float* __restrict__ buf, float* __restrict__ out)
{
    __shared__ float s[SEG];
    __shared__ float sv_lo[BLK], sv_hi[BLK];

    const int t = threadIdx.x;
    const int b = blockIdx.x;
    const int base = b * SEG;
    const int gtid = b * BLK + t;

    // ---- stage raw segment (float4, coalesced) ----
    {
        const float4* in4 = (const float4*)(buf + base);
        float4* s4 = (float4*)s;
        for (int i = t; i < SEG / 4; i += BLK) s4[i] = in4[i];
    }
    __syncthreads();

    const RParams rp = get_params(p);
    const float a_lo = rp.a_lo, d_lo = 1.0f - rp.a_lo;
    const float a_hi = rp.a_hi, d_hi = 1.0f - rp.a_hi;

    // ---- phase 1: per-thread partials (zero init), in-block affine scan ----
    {
        float ylo = 0.0f, yhi = 0.0f;
        const int off = t * M_PER;
#pragma unroll
        for (int k = 0; k < M_PER; k++) {
            float x = s[off + k];
            ylo = fmaf(a_lo, x, d_lo * ylo);
            yhi = fmaf(a_hi, x, d_hi * yhi);
        }
        sv_lo[t] = ylo;
        sv_hi[t] = yhi;
    }

    // D = d^M_PER
    float Plo = 1.0f, Phi = 1.0f;
#pragma unroll
    for (int k = 0; k < M_PER; k++) { Plo *= d_lo; Phi *= d_hi; }
    __syncthreads();

    // inclusive affine scan over 480 threads: 9 rounds (gap up to 256)
    float lad_lo[9], lad_hi[9];
#pragma unroll
    for (int r = 0; r < 9; r++) {
        lad_lo[r] = Plo; lad_hi[r] = Phi;           // D^(2^r)
        const int gap = 1 << r;
        float mylo = sv_lo[t], myhi = sv_hi[t];
        float olo = 0.0f, ohi = 0.0f;
        if (t >= gap) { olo = sv_lo[t - gap]; ohi = sv_hi[t - gap]; }
        __syncthreads();
        sv_lo[t] = fmaf(Plo, olo, mylo);
        sv_hi[t] = fmaf(Phi, ohi, myhi);
        __syncthreads();
        Plo *= Plo; Phi *= Phi;
    }

    // exclusive prefix + D^t (into registers BEFORE sv gets reused)
    const float vex_lo = (t == 0) ? 0.0f : sv_lo[t - 1];
    const float vex_hi = (t == 0) ? 0.0f : sv_hi[t - 1];
    float pex_lo = 1.0f, pex_hi = 1.0f;
#pragma unroll
    for (int r = 0; r < 9; r++)
        if ((t >> r) & 1) { pex_lo *= lad_lo[r]; pex_hi *= lad_hi[r]; }

    if (t == BLK - 1) {
        g_bpart_lo[b] = sv_lo[t];
        g_bpart_hi[b] = sv_hi[t];
    }

    grid_barrier(&g_bar0);

    // ---- phase 2: parallel scan of 125 block partials (every block, redundant)
    // block decay B = D^480 = D^256 * D^128 * D^64 * D^32
    const float Bl = lad_lo[8] * lad_lo[7] * lad_lo[6] * lad_lo[5];
    const float Bh = lad_hi[8] * lad_hi[7] * lad_hi[6] * lad_hi[5];
    {
        float vlo = 0.0f, vhi = 0.0f;
        if (t < NBLK) { vlo = g_bpart_lo[t]; vhi = g_bpart_hi[t]; }
        sv_lo[t] = vlo;
        sv_hi[t] = vhi;
        __syncthreads();
#pragma unroll
        for (int r = 0; r < 7; r++) {               // gap up to 64 covers 125
            const int gap = 1 << r;
            float mylo = sv_lo[t], myhi = sv_hi[t];
            float olo = 0.0f, ohi = 0.0f;
            if (t >= gap && t < NBLK) { olo = sv_lo[t - gap]; ohi = sv_hi[t - gap]; }
            __syncthreads();
            sv_lo[t] = fmaf(Bl, olo, mylo);
            sv_hi[t] = fmaf(Bh, ohi, myhi);
            __syncthreads();
        }
    }
    // this block's exclusive carry
    const float Cb_lo = (b == 0) ? 0.0f : sv_lo[b - 1];
    const float Cb_hi = (b == 0) ? 0.0f : sv_hi[b - 1];
    __syncthreads();

    // ---- replay with exact carry, write filtered = y_hi - y_lo ----
    {
        float ylo = fmaf(pex_lo, Cb_lo, vex_lo);
        float yhi = fmaf(pex_hi, Cb_hi, vex_hi);
        const int off = t * M_PER;
#pragma unroll
        for (int k = 0; k < M_PER; k++) {
            float x = s[off + k];
            ylo = fmaf(a_lo, x, d_lo * ylo);
            yhi = fmaf(a_hi, x, d_hi * yhi);
            s[off + k] = yhi - ylo;
        }
    }
    __syncthreads();
    {
        float4* f4 = (float4*)(g_filt + base);
        const float4* s4 = (const float4*)s;
        for (int i = t; i < SEG / 4; i += BLK) f4[i] = s4[i];
    }

    grid_barrier(&g_bar1);

    // ---- phase 3: comb + tanh ----
    const float fb = rp.fb, gain = rp.gain;

    if (rp.L == CHN && rp.nd == NDEL) {
        // fast path: per-chain stride-L recurrence
        // T[j] = fb*(f[j-1] + T[j-1]) - fb^50 * f[j-50]   (tail when j>=50)
        const int q = gtid / CHN;                   // subchain index (0..24)
        const int c = gtid - q * CHN;               // chain id (coalesced in warp)
        const int j0 = q * SUBLEN;                  // 200 = 25*8, no ragged tail

        // fb^50 by squaring
        const float fp2 = fb * fb;
        const float fp4 = fp2 * fp2;
        const float fp8 = fp4 * fp4;
        const float fp16 = fp8 * fp8;
        const float fb25 = fp16 * fp8 * fb;
        const float fb50 = fb25 * fb25;

        const float* __restrict__ fc = g_filt + c;
        const float* __restrict__ ic = in_sig + c;

        // ---- register preload: all loads independent, MLP ~ 3*SUBLEN ----
        float fv[SUBLEN];   // f[j0+jj]
        float tl[SUBLEN];   // f[j0+jj-50] (0 if j<50)
        float iv[SUBLEN];   // in_sig at n = c + (j0+jj)*CHN
#pragma unroll
        for (int jj = 0; jj < SUBLEN; jj++) {
            const int j = j0 + jj;
            fv[jj] = __ldg(fc + j * CHN);
            tl[jj] = (j >= NDEL) ? __ldg(fc + (j - NDEL) * CHN) : 0.0f;
            iv[jj] = __ldg(ic + j * CHN);
        }

        // startup: T[j0] = sum_{i=1..min(49,j0)} fb^i f[j0-i], MLP=8
        float T;
        {
            const int im = min(NDEL - 1, j0);
            const float fb3 = fp2 * fb;
            const float fb5 = fp4 * fb, fb6 = fp4 * fp2, fb7 = fp4 * fb3;
            float s0 = 0.f, s1 = 0.f, s2 = 0.f, s3 = 0.f;
            float s4 = 0.f, s5 = 0.f, s6 = 0.f, s7 = 0.f;
            float w = fb;
            int i = 1;
            for (; i + 7 <= im; i += 8) {
                const float* qp = fc + (j0 - i) * CHN;
                s0 = fmaf(w,        __ldg(qp),           s0);
                s1 = fmaf(w * fb,   __ldg(qp - CHN),     s1);
                s2 = fmaf(w * fp2,  __ldg(qp - 2 * CHN), s2);
                s3 = fmaf(w * fb3,  __ldg(qp - 3 * CHN), s3);
                s4 = fmaf(w * fp4,  __ldg(qp - 4 * CHN), s4);
                s5 = fmaf(w * fb5,  __ldg(qp - 5 * CHN), s5);
                s6 = fmaf(w * fb6,  __ldg(qp - 6 * CHN), s6);
                s7 = fmaf(w * fb7,  __ldg(qp - 7 * CHN), s7);
                w *= fp8;
            }
            for (; i <= im; i++) {
                s0 = fmaf(w, __ldg(fc + (j0 - i) * CHN), s0);
                w *= fb;
            }
            T = ((s0 + s1) + (s2 + s3)) + ((s4 + s5) + (s6 + s7));
        }

        // all-register recurrence + outputs
        out[c + j0 * CHN] = fast_tanh((iv[0] + T) * gain);
#pragma unroll
        for (int jj = 1; jj < SUBLEN; jj++) {
            T = fmaf(fb, fv[jj - 1] + T, -fb50 * tl[jj]);
            out[c + (j0 + jj) * CHN] = fast_tanh((iv[jj] + T) * gain);
        }
    } else {
        // generic fallback: direct gather, grid-stride
        const int L = rp.L;
        const float fb2 = fb * fb, fb3 = fb2 * fb, fb4 = fb2 * fb2;
        for (int n = gtid; n < NSAMP; n += NTHREADS) {
            const int imax = min(rp.nd - 1, n / L);
            const float* __restrict__ basep = g_filt + n;
            float s0 = 0.0f, s1 = 0.0f, s2 = 0.0f, s3 = 0.0f;
            float w = fb;
            int i = 1;
            for (; i + 3 <= imax; i += 4) {
                const float* qp = basep - i * L;
                s0 = fmaf(w,       __ldg(qp),         s0);
                s1 = fmaf(w * fb,  __ldg(qp - L),     s1);
                s2 = fmaf(w * fb2, __ldg(qp - 2 * L), s2);
                s3 = fmaf(w * fb3, __ldg(qp - 3 * L), s3);
                w *= fb4;
            }
            for (; i <= imax; i++) {
                s0 = fmaf(w, __ldg(basep - i * L), s0);
                w *= fb;
            }
            float sum = __ldg(in_sig + n) + ((s0 + s1) + (s2 + s3));
            out[n] = fast_tanh(sum * gain);
        }
    }

    // ---- reset barriers for the next graph replay ----
    __syncthreads();
    if (t == 0) {
        unsigned int tk = atomicAdd(&g_bar2, 1u);
        if (tk == (unsigned)(NBLK - 1)) {
            g_bar0 = 0; g_bar1 = 0; g_bar2 = 0;
        }
    }
}

// ---------------------------------------------------------------------------
extern "C" void kernel_launch(void* const* d_in, const int* in_sizes, int n_in,
                              void* d_out, int out_size)
{
    const float* input_signal = (const float*)d_in[0];
    const float* parameters   = (const float*)d_in[1];
    const float* delay_buffer = (const float*)d_in[2];
    float* out = (float*)d_out;

    resonator_fused<<<NBLK, BLK>>>(input_signal, parameters, delay_buffer, out);
}

// round 17
// speedup vs baseline: 1.4742x; 1.0404x over previous
#include <cuda_runtime.h>
#include <math.h>

#define NSAMP   480000
#define SRATE   48000.0f
#define MAXDEL  50
#define BLK     480                 // 15 warps/SM -> occupancy cap ~23%
#define NBLK    125                 // <= 148 SMs -> all CTAs co-resident (grid-sync safe)
#define M_PER   8                   // NSAMP / (NBLK*BLK)
#define SEG     (BLK * M_PER)       // 3840 samples per block
#define NTHREADS (NBLK * BLK)       // 60000

// comb fast-path constants (hold for this dataset: p0 in [0,1) -> freq clips to 20)
#define CHN     2400                // L
#define CLEN    200                 // NSAMP / L
#define NDEL    50                  // min(CLEN, MAXDEL)
#define PQ      25                  // subchains per chain (25*2400 = 60000 = NTHREADS)
#define SUBLEN  8                   // CLEN / PQ exactly

// scratch (static device globals — no allocation)
__device__ float g_bpart_lo[NBLK];
__device__ float g_bpart_hi[NBLK];
__device__ float g_filt[NSAMP];
__device__ unsigned int g_bar0 = 0;
__device__ unsigned int g_bar1 = 0;
__device__ unsigned int g_bar2 = 0;

struct RParams {
    float a_lo, a_hi, fb, gain;
    int L, nd;
};

__device__ __forceinline__ RParams get_params(const float* __restrict__ p) {
    RParams r;
    float freq = fminf(fmaxf(p[0], 20.0f), SRATE * 0.5f);
    r.fb   = fminf(fmaxf(p[1], 0.0f), 0.99f);
    r.a_lo = fminf(fmaxf(p[2], 1e-7f), 0.99f);
    r.a_hi = fminf(fmaxf(p[3], 1e-7f), 0.99f);
    r.gain = fmaxf(p[4], 1e-7f);
    float dl = floorf(SRATE / freq);
    dl = fminf(fmaxf(dl, 1.0f), (float)(NSAMP / 2));
    r.L = (int)dl;
    int nd = NSAMP / r.L;
    r.nd = nd < MAXDEL ? nd : MAXDEL;
    return r;
}

__device__ __forceinline__ float fast_tanh(float x) {
    float y;
    asm("tanh.approx.f32 %0, %1;" : "=f"(y) : "f"(x));
    return y;
}

// grid-wide barrier: all 125 CTAs are resident, so spinning is deadlock-free.
__device__ __forceinline__ void grid_barrier(unsigned int* ctr) {
    __threadfence();
    __syncthreads();
    if (threadIdx.x == 0) {
        atomicAdd(ctr, 1u);
        while (*(volatile unsigned int*)ctr < (unsigned)NBLK) { }
    }
    __syncthreads();
    __threadfence();
}

__global__ __launch_bounds__(BLK) void resonator_fused(
    const float* __restrict__ in_sig, const float* __restrict__ p,
    const float* __restrict__ buf, float* __restrict__ out)
{
    __shared__ float s[SEG];
    __shared__ float sv_lo[BLK], sv_hi[BLK];

    const int t = threadIdx.x;
    const int b = blockIdx.x;
    const int base = b * SEG;
    const int gtid = b * BLK + t;

    // fast-path thread mapping (computed up front; used for early iv preload)
    const int q_sc = gtid / CHN;                // subchain index (0..24)
    const int c_ch = gtid - q_sc * CHN;         // chain id (coalesced in warp)
    const int j0_sc = q_sc * SUBLEN;

    // ---- stage raw segment (float4, coalesced) ----
    {
        const float4* in4 = (const float4*)(buf + base);
        float4* s4 = (float4*)s;
        for (int i = t; i < SEG / 4; i += BLK) s4[i] = in4[i];
    }

    // ---- EARLY preload of in_sig for phase 3 (pure input, independent of
    // everything computed) — overlaps its DRAM latency with phases 1-2 ----
    float iv[SUBLEN];
    {
        const float* __restrict__ ic = in_sig + c_ch;
#pragma unroll
        for (int jj = 0; jj < SUBLEN; jj++)
            iv[jj] = __ldg(ic + (j0_sc + jj) * CHN);
    }
    __syncthreads();

    const RParams rp = get_params(p);
    const float a_lo = rp.a_lo, d_lo = 1.0f - rp.a_lo;
    const float a_hi = rp.a_hi, d_hi = 1.0f - rp.a_hi;

    // ---- phase 1: per-thread partials (zero init), in-block affine scan ----
    {
        float ylo = 0.0f, yhi = 0.0f;
        const int off = t * M_PER;
#pragma unroll
        for (int k = 0; k < M_PER; k++) {
            float x = s[off + k];
            ylo = fmaf(a_lo, x, d_lo * ylo);
            yhi = fmaf(a_hi, x, d_hi * yhi);
        }
        sv_lo[t] = ylo;
        sv_hi[t] = yhi;
    }

    // D = d^M_PER
    float Plo = 1.0f, Phi = 1.0f;
#pragma unroll
    for (int k = 0; k < M_PER; k++) { Plo *= d_lo; Phi *= d_hi; }
    __syncthreads();

    // inclusive affine scan over 480 threads: 9 rounds (gap up to 256)
    float lad_lo[9], lad_hi[9];
#pragma unroll
    for (int r = 0; r < 9; r++) {
        lad_lo[r] = Plo; lad_hi[r] = Phi;           // D^(2^r)
        const int gap = 1 << r;
        float mylo = sv_lo[t], myhi = sv_hi[t];
        float olo = 0.0f, ohi = 0.0f;
        if (t >= gap) { olo = sv_lo[t - gap]; ohi = sv_hi[t - gap]; }
        __syncthreads();
        sv_lo[t] = fmaf(Plo, olo, mylo);
        sv_hi[t] = fmaf(Phi, ohi, myhi);
        __syncthreads();
        Plo *= Plo; Phi *= Phi;
    }

    // exclusive prefix + D^t (into registers BEFORE sv gets reused)
    const float vex_lo = (t == 0) ? 0.0f : sv_lo[t - 1];
    const float vex_hi = (t == 0) ? 0.0f : sv_hi[t - 1];
    float pex_lo = 1.0f, pex_hi = 1.0f;
#pragma unroll
    for (int r = 0; r < 9; r++)
        if ((t >> r) & 1) { pex_lo *= lad_lo[r]; pex_hi *= lad_hi[r]; }

    if (t == BLK - 1) {
        g_bpart_lo[b] = sv_lo[t];
        g_bpart_hi[b] = sv_hi[t];
    }

    grid_barrier(&g_bar0);

    // ---- phase 2: parallel scan of 125 block partials (every block, redundant)
    // block decay B = D^480 = D^256 * D^128 * D^64 * D^32
    const float Bl = lad_lo[8] * lad_lo[7] * lad_lo[6] * lad_lo[5];
    const float Bh = lad_hi[8] * lad_hi[7] * lad_hi[6] * lad_hi[5];
    {
        float vlo = 0.0f, vhi = 0.0f;
        if (t < NBLK) { vlo = g_bpart_lo[t]; vhi = g_bpart_hi[t]; }
        sv_lo[t] = vlo;
        sv_hi[t] = vhi;
        __syncthreads();
#pragma unroll
        for (int r = 0; r < 7; r++) {               // gap up to 64 covers 125
            const int gap = 1 << r;
            float mylo = sv_lo[t], myhi = sv_hi[t];
            float olo = 0.0f, ohi = 0.0f;
            if (t >= gap && t < NBLK) { olo = sv_lo[t - gap]; ohi = sv_hi[t - gap]; }
            __syncthreads();
            sv_lo[t] = fmaf(Bl, olo, mylo);
            sv_hi[t] = fmaf(Bh, ohi, myhi);
            __syncthreads();
        }
    }
    // this block's exclusive carry
    const float Cb_lo = (b == 0) ? 0.0f : sv_lo[b - 1];
    const float Cb_hi = (b == 0) ? 0.0f : sv_hi[b - 1];
    __syncthreads();

    // ---- replay with exact carry, write filtered = y_hi - y_lo ----
    {
        float ylo = fmaf(pex_lo, Cb_lo, vex_lo);
        float yhi = fmaf(pex_hi, Cb_hi, vex_hi);
        const int off = t * M_PER;
#pragma unroll
        for (int k = 0; k < M_PER; k++) {
            float x = s[off + k];
            ylo = fmaf(a_lo, x, d_lo * ylo);
            yhi = fmaf(a_hi, x, d_hi * yhi);
            s[off + k] = yhi - ylo;
        }
    }
    __syncthreads();
    {
        float4* f4 = (float4*)(g_filt + base);
        const float4* s4 = (const float4*)s;
        for (int i = t; i < SEG / 4; i += BLK) f4[i] = s4[i];
    }

    grid_barrier(&g_bar1);

    // ---- phase 3: comb + tanh ----
    const float fb = rp.fb, gain = rp.gain;

    if (rp.L == CHN && rp.nd == NDEL) {
        // fast path: per-chain stride-L recurrence
        // T[j] = fb*(f[j-1] + T[j-1]) - fb^50 * f[j-50]   (tail when j>=50)
        const int q = q_sc, c = c_ch, j0 = j0_sc;

        // fb powers by squaring
        const float fp2 = fb * fb;
        const float fp4 = fp2 * fp2;
        const float fp8 = fp4 * fp4;
        const float fp16 = fp8 * fp8;
        const float fb25 = fp16 * fp8 * fb;
        const float fb50 = fb25 * fb25;

        const float* __restrict__ fc = g_filt + c;

        // ---- register preload (independent loads, high MLP) ----
        float fv[SUBLEN];   // f[j0+jj]
        float tl[SUBLEN];   // f[j0+jj-50] (0 if j<50)
#pragma unroll
        for (int jj = 0; jj < SUBLEN; jj++) {
            const int j = j0 + jj;
            fv[jj] = __ldg(fc + j * CHN);
            tl[jj] = (j >= NDEL) ? __ldg(fc + (j - NDEL) * CHN) : 0.0f;
        }

        // ---- startup: T[j0] = sum_{i=1..min(49,j0)} fb^i f[j0-i] ----
        // fully unrolled predicated loads: all 49 issue independently (MLP~49),
        // then an 8-accumulator weighted reduction.
        float T;
        {
            const int im = min(NDEL - 1, j0);       // 0, 8, 16, ... or 49
            float g[NDEL - 1];                      // g[i-1] = f[j0-i] (0 if inactive)
#pragma unroll
            for (int i = 1; i < NDEL; i++)
                g[i - 1] = (i <= im) ? __ldg(fc + (j0 - i) * CHN) : 0.0f;

            const float fb3 = fp2 * fb;
            const float fb5 = fp4 * fb, fb6 = fp4 * fp2, fb7 = fp4 * fb3;
            float s0 = 0.f, s1 = 0.f, s2 = 0.f, s3 = 0.f;
            float s4 = 0.f, s5 = 0.f, s6 = 0.f, s7 = 0.f;
            float w = fb;                           // fb^(8k+1)
#pragma unroll
            for (int k8 = 0; k8 < 6; k8++) {        // covers i = 1..48
                const int ibase = 8 * k8;
                s0 = fmaf(w,       g[ibase + 0], s0);
                s1 = fmaf(w * fb,  g[ibase + 1], s1);
                s2 = fmaf(w * fp2, g[ibase + 2], s2);
                s3 = fmaf(w * fb3, g[ibase + 3], s3);
                s4 = fmaf(w * fp4, g[ibase + 4], s4);
                s5 = fmaf(w * fb5, g[ibase + 5], s5);
                s6 = fmaf(w * fb6, g[ibase + 6], s6);
                s7 = fmaf(w * fb7, g[ibase + 7], s7);
                w *= fp8;
            }
            s0 = fmaf(w, g[48], s0);                // i = 49
            T = ((s0 + s1) + (s2 + s3)) + ((s4 + s5) + (s6 + s7));
        }

        // all-register recurrence + outputs
        out[c + j0 * CHN] = fast_tanh((iv[0] + T) * gain);
#pragma unroll
        for (int jj = 1; jj < SUBLEN; jj++) {
            T = fmaf(fb, fv[jj - 1] + T, -fb50 * tl[jj]);
            out[c + (j0 + jj) * CHN] = fast_tanh((iv[jj] + T) * gain);
        }
    } else {
        // generic fallback: direct gather, grid-stride
        const int L = rp.L;
        const float fb2 = fb * fb, fb3 = fb2 * fb, fb4 = fb2 * fb2;
        for (int n = gtid; n < NSAMP; n += NTHREADS) {
            const int imax = min(rp.nd - 1, n / L);
            const float* __restrict__ basep = g_filt + n;
            float s0 = 0.0f, s1 = 0.0f, s2 = 0.0f, s3 = 0.0f;
            float w = fb;
            int i = 1;
            for (; i + 3 <= imax; i += 4) {
                const float* qp = basep - i * L;
                s0 = fmaf(w,       __ldg(qp),         s0);
                s1 = fmaf(w * fb,  __ldg(qp - L),     s1);
                s2 = fmaf(w * fb2, __ldg(qp - 2 * L), s2);
                s3 = fmaf(w * fb3, __ldg(qp - 3 * L), s3);
                w *= fb4;
            }
            for (; i <= imax; i++) {
                s0 = fmaf(w, __ldg(basep - i * L), s0);
                w *= fb;
            }
            float sum = __ldg(in_sig + n) + ((s0 + s1) + (s2 + s3));
            out[n] = fast_tanh(sum * gain);
        }
    }

    // ---- reset barriers for the next graph replay ----
    __syncthreads();
    if (t == 0) {
        unsigned int tk = atomicAdd(&g_bar2, 1u);
        if (tk == (unsigned)(NBLK - 1)) {
            g_bar0 = 0; g_bar1 = 0; g_bar2 = 0;
        }
    }
}

// ---------------------------------------------------------------------------
extern "C" void kernel_launch(void* const* d_in, const int* in_sizes, int n_in,
                              void* d_out, int out_size)
{
    const float* input_signal = (const float*)d_in[0];
    const float* parameters   = (const float*)d_in[1];
    const float* delay_buffer = (const float*)d_in[2];
    float* out = (float*)d_out;

    resonator_fused<<<NBLK, BLK>>>(input_signal, parameters, delay_buffer, out);
}